// round 14
// baseline (speedup 1.0000x reference)
#include <cuda_runtime.h>
#include <cuda_bf16.h>
#include <cstdint>
#include <math.h>

// Problem dims
#define BQ   128
#define TQ   512
#define HQ   512
#define N3   1536        // 3*H
#define D1   320         // LAT + F2
#define MROWS 65536      // B*T

// ---------------- scratch (__device__ globals; no runtime alloc) ----------------
__device__ __nv_bfloat16 g_Xhi[(size_t)MROWS * D1];
__device__ __nv_bfloat16 g_Xlo[(size_t)MROWS * D1];
__device__ float         g_xW [(size_t)MROWS * N3];      // reused for xW5 then xW6
__device__ __nv_bfloat16 g_g5hi[(size_t)MROWS * HQ];
__device__ __nv_bfloat16 g_g5lo[(size_t)MROWS * HQ];
__device__ __nv_bfloat16 g_g6hi[(size_t)MROWS * HQ];
__device__ __nv_bfloat16 g_g6lo[(size_t)MROWS * HQ];
__device__ __nv_bfloat16 g_W5t_hi[N3 * D1], g_W5t_lo[N3 * D1];   // [n][k]
__device__ __nv_bfloat16 g_U5t_hi[N3 * HQ], g_U5t_lo[N3 * HQ];
__device__ __nv_bfloat16 g_W6t_hi[N3 * HQ], g_W6t_lo[N3 * HQ];
__device__ __nv_bfloat16 g_U6t_hi[N3 * HQ], g_U6t_lo[N3 * HQ];
__device__ unsigned g_ctr2[2][8];      // per (phase, batch-group) barrier counters

// ---------------- helpers ----------------
__device__ __forceinline__ void bsplit(float v, __nv_bfloat16& hi, __nv_bfloat16& lo) {
    hi = __float2bfloat16_rn(v);
    lo = __float2bfloat16_rn(v - __bfloat162float(hi));
}
__device__ __forceinline__ float hsig(float x) {
    return fminf(fmaxf(0.2f * x + 0.5f, 0.0f), 1.0f);
}

#define MMA16816(C, A, Bf) asm volatile( \
    "mma.sync.aligned.m16n8k16.row.col.f32.bf16.bf16.f32 " \
    "{%0,%1,%2,%3},{%4,%5,%6,%7},{%8,%9},{%0,%1,%2,%3};\n" \
    : "+f"(C[0]), "+f"(C[1]), "+f"(C[2]), "+f"(C[3]) \
    : "r"(A[0]), "r"(A[1]), "r"(A[2]), "r"(A[3]), "r"((Bf)[0]), "r"((Bf)[1]))

#define LDSM4(R, ADDR) asm volatile( \
    "ldmatrix.sync.aligned.m8n8.x4.shared.b16 {%0,%1,%2,%3}, [%4];" \
    : "=r"((R)[0]), "=r"((R)[1]), "=r"((R)[2]), "=r"((R)[3]) : "r"(ADDR))

// ---------------- prep: weight transposes + hi/lo split + counter reset ----------------
__global__ void prep_kernel(const float* __restrict__ W5, const float* __restrict__ U5,
                            const float* __restrict__ W6, const float* __restrict__ U6) {
    int i = blockIdx.x * blockDim.x + threadIdx.x;
    if (i < 16) ((unsigned*)g_ctr2)[i] = 0u;
    const int nW5 = N3 * D1;        // 491520
    const int nU  = N3 * HQ;        // 786432
    if (i < nW5) {
        int n = i / D1, k = i % D1;
        bsplit(W5[k * N3 + n], g_W5t_hi[i], g_W5t_lo[i]);
    } else if (i < nW5 + nU) {
        int j = i - nW5; int n = j / HQ, k = j % HQ;
        bsplit(U5[k * N3 + n], g_U5t_hi[j], g_U5t_lo[j]);
    } else if (i < nW5 + 2 * nU) {
        int j = i - nW5 - nU; int n = j / HQ, k = j % HQ;
        bsplit(W6[k * N3 + n], g_W6t_hi[j], g_W6t_lo[j]);
    } else if (i < nW5 + 3 * nU) {
        int j = i - nW5 - 2 * nU; int n = j / HQ, k = j % HQ;
        bsplit(U6[k * N3 + n], g_U6t_hi[j], g_U6t_lo[j]);
    }
}

// ---------------- build X = concat(repeat(z), x2) * masks, split to bf16 hi/lo ----------------
// Vectorized: one thread handles 8 consecutive features (float4 x2 in, uint4 out).
__global__ void __launch_bounds__(256) build_x_kernel(const float* __restrict__ z,
                                                      const float* __restrict__ x2,
                                                      const float* __restrict__ masks) {
    int i = blockIdx.x * blockDim.x + threadIdx.x;      // 0 .. MROWS*40-1
    if (i >= MROWS * (D1 / 8)) return;
    int row = i / 40, cb = i - row * 40;
    int c0 = cb * 8;
    float m = masks[row];
    const float* src = (c0 < 256) ? (z + ((row >> 9) << 8) + c0)
                                  : (x2 + (size_t)row * 64 + (c0 - 256));
    float4 v0 = ((const float4*)src)[0];
    float4 v1 = ((const float4*)src)[1];
    float vv[8] = {v0.x, v0.y, v0.z, v0.w, v1.x, v1.y, v1.z, v1.w};
    __nv_bfloat16 h[8], l[8];
#pragma unroll
    for (int j = 0; j < 8; j++) bsplit(vv[j] * m, h[j], l[j]);
    size_t off = ((size_t)row * D1 + c0) / 8;
    ((uint4*)g_Xhi)[off] = *(uint4*)h;
    ((uint4*)g_Xlo)[off] = *(uint4*)l;
}

// ---------------- feedforward GEMM: g_xW = A(hi,lo) @ Wt(hi,lo)^T + bias ----------------
// Grid (24 n-tiles, 512 m-tiles) for L2 reuse of A. Block tile 128(M) x 64(N),
// BK=32, 256 threads (8 warps 4x2, warp tile 32x32). smem rows are 128B with
// 16B-chunk XOR swizzle; fragments via ldmatrix.x4 (same mapping as gru_rec).
// Register-prefetch pipeline for the next BK tile.
__global__ void __launch_bounds__(256) gemm_ff(int phase, const float* __restrict__ bias) {
    const int K = phase ? HQ : D1;
    const __nv_bfloat16* Ahi = phase ? g_g5hi : g_Xhi;
    const __nv_bfloat16* Alo = phase ? g_g5lo : g_Xlo;
    const __nv_bfloat16* Whi = phase ? g_W6t_hi : g_W5t_hi;
    const __nv_bfloat16* Wlo = phase ? g_W6t_lo : g_W5t_lo;

    __shared__ __nv_bfloat16 sAh[128 * 64], sAl[128 * 64];   // 16 KB each (128B rows)
    __shared__ __nv_bfloat16 sWh[64 * 64],  sWl[64 * 64];    // 8 KB each

    int tid = threadIdx.x;
    int row0 = blockIdx.y * 128, n0 = blockIdx.x * 64;
    int warp = tid >> 5, lane = tid & 31, g = lane >> 2, tg = lane & 3;
    int wm = warp >> 1, wn = warp & 1;
    int rm = lane & 7, jq = lane >> 3;
    int ahh = jq >> 1, bkk = jq & 1;
    int aRowL = rm + ((jq & 1) << 3);
    int bRowL = rm + ((jq >> 1) << 3);

    const unsigned bAh = (unsigned)__cvta_generic_to_shared(sAh);
    const unsigned bAl = (unsigned)__cvta_generic_to_shared(sAl);
    const unsigned bWh = (unsigned)__cvta_generic_to_shared(sWh);
    const unsigned bWl = (unsigned)__cvta_generic_to_shared(sWl);
    unsigned aOff[2], bOff[2];
#pragma unroll
    for (int mt = 0; mt < 2; mt++) aOff[mt] = (unsigned)((wm * 32 + mt * 16 + aRowL) * 128);
#pragma unroll
    for (int nh = 0; nh < 2; nh++) bOff[nh] = (unsigned)((wn * 32 + nh * 16 + bRowL) * 128);

    // staging indices: each thread stages A rows r1, r1+64 (chunk c1) and W row r1
    int r1 = tid >> 2, c1 = tid & 3;
    int swc = c1 ^ (r1 & 7);                       // (r1+64)&7 == r1&7
    unsigned stA1 = (unsigned)(r1 * 128 + swc * 16);
    unsigned stA2 = (unsigned)((r1 + 64) * 128 + swc * 16);
    unsigned stW  = stA1;

    float C[2][4][4];
#pragma unroll
    for (int a = 0; a < 2; a++)
#pragma unroll
        for (int b = 0; b < 4; b++)
#pragma unroll
            for (int c = 0; c < 4; c++) C[a][b][c] = 0.0f;

    const int nk2 = K / 32;
    uint4 ra0, ra1, rb0, rb1, rw, rv;

#define FF_LOAD(KT) do { \
        int k0 = (KT) * 32; \
        ra0 = *((const uint4*)Ahi + ((size_t)(row0 + r1) * K + k0) / 8 + c1); \
        ra1 = *((const uint4*)Ahi + ((size_t)(row0 + r1 + 64) * K + k0) / 8 + c1); \
        rb0 = *((const uint4*)Alo + ((size_t)(row0 + r1) * K + k0) / 8 + c1); \
        rb1 = *((const uint4*)Alo + ((size_t)(row0 + r1 + 64) * K + k0) / 8 + c1); \
        rw  = *((const uint4*)Whi + ((size_t)(n0 + r1) * K + k0) / 8 + c1); \
        rv  = *((const uint4*)Wlo + ((size_t)(n0 + r1) * K + k0) / 8 + c1); \
    } while (0)

    FF_LOAD(0);
    for (int kt = 0; kt < nk2; kt++) {
        *(uint4*)((char*)sAh + stA1) = ra0;
        *(uint4*)((char*)sAh + stA2) = ra1;
        *(uint4*)((char*)sAl + stA1) = rb0;
        *(uint4*)((char*)sAl + stA2) = rb1;
        *(uint4*)((char*)sWh + stW)  = rw;
        *(uint4*)((char*)sWl + stW)  = rv;
        __syncthreads();
        if (kt + 1 < nk2) FF_LOAD(kt + 1);   // overlaps MMAs below

#pragma unroll
        for (int kk = 0; kk < 2; kk++) {
            uint32_t ah4[2][4], al4[2][4], bh4[2][4], bl4[2][4];
            unsigned ac = (unsigned)(((kk * 2 + ahh) ^ rm) * 16);
            unsigned bc = (unsigned)(((kk * 2 + bkk) ^ rm) * 16);
#pragma unroll
            for (int mt = 0; mt < 2; mt++) {
                LDSM4(ah4[mt], bAh + aOff[mt] + ac);
                LDSM4(al4[mt], bAl + aOff[mt] + ac);
            }
#pragma unroll
            for (int nh = 0; nh < 2; nh++) {
                LDSM4(bh4[nh], bWh + bOff[nh] + bc);
                LDSM4(bl4[nh], bWl + bOff[nh] + bc);
            }
#pragma unroll
            for (int mt = 0; mt < 2; mt++)
#pragma unroll
                for (int nh = 0; nh < 2; nh++)
#pragma unroll
                    for (int hf = 0; hf < 2; hf++) {
                        int nt = nh * 2 + hf;
                        MMA16816(C[mt][nt], ah4[mt], bh4[nh] + 2 * hf);
                        MMA16816(C[mt][nt], ah4[mt], bl4[nh] + 2 * hf);
                        MMA16816(C[mt][nt], al4[mt], bh4[nh] + 2 * hf);
                    }
        }
        __syncthreads();
    }
    // epilogue: + bias, store fp32
#pragma unroll
    for (int mt = 0; mt < 2; mt++) {
#pragma unroll
        for (int nt = 0; nt < 4; nt++) {
            int m = row0 + wm * 32 + mt * 16 + g;
            int n = n0 + wn * 32 + nt * 8 + tg * 2;
            float b0v = bias[n], b1v = bias[n + 1];
            g_xW[(size_t)m * N3 + n]           = C[mt][nt][0] + b0v;
            g_xW[(size_t)m * N3 + n + 1]       = C[mt][nt][1] + b1v;
            g_xW[(size_t)(m + 8) * N3 + n]     = C[mt][nt][2] + b0v;
            g_xW[(size_t)(m + 8) * N3 + n + 1] = C[mt][nt][3] + b1v;
        }
    }
}

// ---------------- persistent GRU recurrence (unchanged from R11) ----------------
#define SM_UHI 0
#define SM_ULO 98304
#define SM_HSH 196608
#define SM_HSL 212992
#define SM_TOTAL 229376
#define INNER_STRIDE 100
#define INNER_BYTES  6400     // 16 rows * 100 floats * 4

__global__ void __launch_bounds__(384, 1) gru_rec(int phase, const float* __restrict__ br) {
    extern __shared__ char sm[];
    const __nv_bfloat16* Uth = phase ? g_U6t_hi : g_U5t_hi;
    const __nv_bfloat16* Utl = phase ? g_U6t_lo : g_U5t_lo;
    const float* __restrict__ xW = g_xW;
    __nv_bfloat16* Ghi = phase ? g_g6hi : g_g5hi;
    __nv_bfloat16* Glo = phase ? g_g6lo : g_g5lo;

    const int tid = threadIdx.x;
    const int warp = tid >> 5, lane = tid & 31;
    const int g = lane >> 2, tg = lane & 3;
    const int bb = (int)blockIdx.x >> 4, fb = (int)blockIdx.x & 15;
    const int b0 = bb * 16, f0 = fb * 32;
    unsigned* ctr = &g_ctr2[phase][bb];

    const int ks  = warp / 6;
    const int w6  = warp % 6;
    const int gi2 = w6 >> 1;
    const int nh  = w6 & 1;
    const int rm  = lane & 7;
    const int jq  = lane >> 3;
    const int arow = rm + ((jq & 1) << 3);
    const int ahh  = jq >> 1;
    const int brow = rm + ((jq >> 1) << 3);
    const int bkk  = jq & 1;
    const int jrow0 = gi2 * 32 + nh * 16;

    const unsigned sm32 = (unsigned)__cvta_generic_to_shared(sm);
    const unsigned aBaseH = sm32 + SM_HSH + arow * 1024;
    const unsigned aBaseL = sm32 + SM_HSL + arow * 1024;
    const unsigned bBaseH = sm32 + SM_UHI + (jrow0 + brow) * 1024;
    const unsigned bBaseL = sm32 + SM_ULO + (jrow0 + brow) * 1024;

    for (int idx = tid; idx < 2 * 96 * 64; idx += 384) {
        int arr = idx >= 96 * 64;
        int e = arr ? (idx - 96 * 64) : idx;
        int j = e >> 6;
        int q = e & 63;
        int sw = q ^ (j & 7);
        int n = (j >> 5) * HQ + f0 + (j & 31);
        uint4 v = ((const uint4*)((arr ? Utl : Uth) + (size_t)n * HQ))[q];
        *(uint4*)(sm + (arr ? SM_ULO : SM_UHI) + j * 1024 + sw * 16) = v;
    }
    float bzv[2], brv[2], bhv[2];
#pragma unroll
    for (int s = 0; s < 2; s++) {
        int e = tid + s * 384;
        if (e < 512) {
            int f = f0 + (e & 31);
            bzv[s] = br[f]; brv[s] = br[512 + f]; bhv[s] = br[1024 + f];
        } else { bzv[s] = brv[s] = bhv[s] = 0.f; }
    }
    __syncthreads();

    float xzv[2], xrv[2], xhv[2], hpv[2];
#pragma unroll
    for (int s = 0; s < 2; s++) {
        int e = tid + s * 384;
        if (e < 512) {
            int r = e >> 5, c = e & 31;
            size_t row = (size_t)(b0 + r) * TQ;
            int f = f0 + c;
            xzv[s] = xW[row * N3 + f];
            xrv[s] = xW[row * N3 + 512 + f];
            xhv[s] = xW[row * N3 + 1024 + f];
        } else { xzv[s] = xrv[s] = xhv[s] = 0.f; }
    }

    for (int t = 0; t < TQ; t++) {
        if (t == 0) {
            for (int idx = tid; idx < 2048; idx += 384) {
                int arr = idx >> 10, e = idx & 1023, r = e >> 6, q = e & 63;
                int sw = q ^ (r & 7);
                *(uint4*)(sm + (arr ? SM_HSL : SM_HSH) + r * 1024 + sw * 16) =
                    make_uint4(0u, 0u, 0u, 0u);
            }
        } else {
            for (int idx = tid; idx < 2048; idx += 384) {
                int arr = idx >> 10, e = idx & 1023, r = e >> 6, q = e & 63;
                int sw = q ^ (r & 7);
                const __nv_bfloat16* src =
                    (arr ? Glo : Ghi) + ((size_t)(b0 + r) * TQ + (t - 1)) * HQ;
                uint4 v = __ldcg((const uint4*)src + q);
                *(uint4*)(sm + (arr ? SM_HSL : SM_HSH) + r * 1024 + sw * 16) = v;
            }
        }
        __syncthreads();

#pragma unroll
        for (int s = 0; s < 2; s++) {
            int e = tid + s * 384;
            hpv[s] = 0.f;
            if (e < 512) {
                int r = e >> 5, c = e & 31;
                int w = (f0 + c) >> 1;
                int sw = w ^ ((r & 7) << 2);
                uint32_t whi = *(uint32_t*)(sm + SM_HSH + r * 1024 + sw * 4);
                uint32_t wlo = *(uint32_t*)(sm + SM_HSL + r * 1024 + sw * 4);
                unsigned short sh = (c & 1) ? (unsigned short)(whi >> 16) : (unsigned short)(whi & 0xffff);
                unsigned short sl = (c & 1) ? (unsigned short)(wlo >> 16) : (unsigned short)(wlo & 0xffff);
                hpv[s] = __bfloat162float(__ushort_as_bfloat16(sh)) +
                         __bfloat162float(__ushort_as_bfloat16(sl));
            }
        }

        float C0[4] = {0.f, 0.f, 0.f, 0.f}, C1[4] = {0.f, 0.f, 0.f, 0.f};
        const int ktBeg = ks * 16, ktEnd = ktBeg + 16;
#pragma unroll 4
        for (int kt = ktBeg; kt < ktEnd; kt++) {
            unsigned aOf = (unsigned)(((2 * kt + ahh) ^ rm) * 16);
            unsigned bOf = (unsigned)(((2 * kt + bkk) ^ rm) * 16);
            uint32_t ah4[4], al4[4], bh4[4], bl4[4];
            LDSM4(ah4, aBaseH + aOf);
            LDSM4(al4, aBaseL + aOf);
            LDSM4(bh4, bBaseH + bOf);
            LDSM4(bl4, bBaseL + bOf);
            MMA16816(C0, ah4, bh4);
            MMA16816(C0, ah4, bl4);
            MMA16816(C0, al4, bh4);
            MMA16816(C1, ah4, bh4 + 2);
            MMA16816(C1, ah4, bl4 + 2);
            MMA16816(C1, al4, bh4 + 2);
        }
        __syncthreads();

        {
            float* innerK = (float*)(sm + SM_HSL + ks * INNER_BYTES);
            int colb = gi2 * 32 + nh * 16 + 2 * tg;
            innerK[g * INNER_STRIDE + colb]            = C0[0];
            innerK[g * INNER_STRIDE + colb + 1]        = C0[1];
            innerK[(g + 8) * INNER_STRIDE + colb]      = C0[2];
            innerK[(g + 8) * INNER_STRIDE + colb + 1]  = C0[3];
            innerK[g * INNER_STRIDE + colb + 8]        = C1[0];
            innerK[g * INNER_STRIDE + colb + 9]        = C1[1];
            innerK[(g + 8) * INNER_STRIDE + colb + 8]  = C1[2];
            innerK[(g + 8) * INNER_STRIDE + colb + 9]  = C1[3];
        }
        __syncthreads();

#pragma unroll
        for (int s = 0; s < 2; s++) {
            int e = tid + s * 384;
            if (e < 512) {
                int r = e >> 5, c = e & 31;
                const float* in0 = (const float*)(sm + SM_HSL);
                const float* in1 = (const float*)(sm + SM_HSL + INNER_BYTES);
                float iz = in0[r * INNER_STRIDE + c]      + in1[r * INNER_STRIDE + c];
                float ir = in0[r * INNER_STRIDE + 32 + c] + in1[r * INNER_STRIDE + 32 + c];
                float ih = in0[r * INNER_STRIDE + 64 + c] + in1[r * INNER_STRIDE + 64 + c];
                float zg = hsig(xzv[s] + iz + bzv[s]);
                float rg = hsig(xrv[s] + ir + brv[s]);
                float hh = tanhf(xhv[s] + rg * (ih + bhv[s]));
                float hn = zg * hpv[s] + (1.0f - zg) * hh;
                size_t row = (size_t)(b0 + r) * TQ + t;
                __nv_bfloat16 hi, lo; bsplit(hn, hi, lo);
                Ghi[row * HQ + f0 + c] = hi;
                Glo[row * HQ + f0 + c] = lo;
            }
        }

        if (t + 1 < TQ) {
#pragma unroll
            for (int s = 0; s < 2; s++) {
                int e = tid + s * 384;
                if (e < 512) {
                    int r = e >> 5, c = e & 31;
                    size_t row = (size_t)(b0 + r) * TQ + (t + 1);
                    int f = f0 + c;
                    xzv[s] = xW[row * N3 + f];
                    xrv[s] = xW[row * N3 + 512 + f];
                    xhv[s] = xW[row * N3 + 1024 + f];
                }
            }
        }

        __syncthreads();
        if (tid == 0) {
            asm volatile("red.release.gpu.global.add.u32 [%0], %1;" :: "l"(ctr), "r"(1u) : "memory");
            unsigned target = (unsigned)(t + 1) * 16u;
            unsigned v;
            do {
                asm volatile("ld.acquire.gpu.u32 %0, [%1];" : "=r"(v) : "l"(ctr));
                if (v >= target) break;
                __nanosleep(16);
            } while (true);
        }
        __syncthreads();
    }
}

// ---------------- final dense(1) + tanh + mask ----------------
__global__ void __launch_bounds__(256) dense_out(const float* __restrict__ Wd,
                                                 const float* __restrict__ bd,
                                                 const float* __restrict__ dmask,
                                                 float* __restrict__ out) {
    __shared__ float w[512];
    int tid = threadIdx.x;
    for (int i = tid; i < 512; i += 256) w[i] = Wd[i];
    __syncthreads();
    int warp = tid >> 5, lane = tid & 31;
    size_t row = (size_t)blockIdx.x * 8 + warp;
    const __nv_bfloat16* ph = g_g6hi + row * HQ;
    const __nv_bfloat16* pl = g_g6lo + row * HQ;
    float s = 0.f;
#pragma unroll 4
    for (int i = lane; i < 512; i += 32)
        s += (__bfloat162float(ph[i]) + __bfloat162float(pl[i])) * w[i];
#pragma unroll
    for (int o = 16; o; o >>= 1) s += __shfl_xor_sync(0xffffffffu, s, o);
    if (lane == 0) out[row] = tanhf(s + bd[0]) * dmask[row];
}

// ---------------- launch ----------------
extern "C" void kernel_launch(void* const* d_in, const int* in_sizes, int n_in,
                              void* d_out, int out_size) {
    const float* z   = (const float*)d_in[0];
    const float* x2  = (const float*)d_in[1];
    const float* msk = (const float*)d_in[2];
    const float* dmk = (const float*)d_in[3];
    const float* W5  = (const float*)d_in[4];
    const float* U5  = (const float*)d_in[5];
    const float* bi5 = (const float*)d_in[6];
    const float* br5 = (const float*)d_in[7];
    const float* W6  = (const float*)d_in[8];
    const float* U6  = (const float*)d_in[9];
    const float* bi6 = (const float*)d_in[10];
    const float* br6 = (const float*)d_in[11];
    const float* Wd  = (const float*)d_in[12];
    const float* bd  = (const float*)d_in[13];
    float* out = (float*)d_out;

    cudaFuncSetAttribute(gru_rec, cudaFuncAttributeMaxDynamicSharedMemorySize, SM_TOTAL);

    prep_kernel<<<11136, 256>>>(W5, U5, W6, U6);
    build_x_kernel<<<10240, 256>>>(z, x2, msk);
    gemm_ff<<<dim3(24, 512), 256>>>(0, bi5);
    gru_rec<<<128, 384, SM_TOTAL>>>(0, br5);
    gemm_ff<<<dim3(24, 512), 256>>>(1, bi6);
    gru_rec<<<128, 384, SM_TOTAL>>>(1, br6);
    dense_out<<<8192, 256>>>(Wd, bd, dmk, out);
}

// round 16
// speedup vs baseline: 1.4048x; 1.4048x over previous
#include <cuda_runtime.h>
#include <cuda_bf16.h>
#include <cstdint>
#include <math.h>

// Problem dims
#define BQ   128
#define TQ   512
#define HQ   512
#define N3   1536        // 3*H
#define D1   320         // LAT + F2
#define MROWS 65536      // B*T

// ---------------- scratch (__device__ globals; no runtime alloc) ----------------
__device__ __nv_bfloat16 g_Xhi[(size_t)MROWS * D1];
__device__ __nv_bfloat16 g_Xlo[(size_t)MROWS * D1];
__device__ float         g_xW [(size_t)MROWS * N3];      // reused for xW5 then xW6
__device__ __nv_bfloat16 g_g5hi[(size_t)MROWS * HQ];
__device__ __nv_bfloat16 g_g5lo[(size_t)MROWS * HQ];
__device__ __nv_bfloat16 g_g6hi[(size_t)MROWS * HQ];
__device__ __nv_bfloat16 g_g6lo[(size_t)MROWS * HQ];
__device__ __nv_bfloat16 g_W5t_hi[N3 * D1], g_W5t_lo[N3 * D1];   // [n][k]
__device__ __nv_bfloat16 g_U5t_hi[N3 * HQ], g_U5t_lo[N3 * HQ];
__device__ __nv_bfloat16 g_W6t_hi[N3 * HQ], g_W6t_lo[N3 * HQ];
__device__ __nv_bfloat16 g_U6t_hi[N3 * HQ], g_U6t_lo[N3 * HQ];
__device__ unsigned g_ctr2[2][8];      // per (phase, batch-group) barrier counters

// ---------------- helpers ----------------
__device__ __forceinline__ void bsplit(float v, __nv_bfloat16& hi, __nv_bfloat16& lo) {
    hi = __float2bfloat16_rn(v);
    lo = __float2bfloat16_rn(v - __bfloat162float(hi));
}
__device__ __forceinline__ float hsig(float x) {
    return fminf(fmaxf(0.2f * x + 0.5f, 0.0f), 1.0f);
}

#define MMA16816(C, A, Bf) asm volatile( \
    "mma.sync.aligned.m16n8k16.row.col.f32.bf16.bf16.f32 " \
    "{%0,%1,%2,%3},{%4,%5,%6,%7},{%8,%9},{%0,%1,%2,%3};\n" \
    : "+f"(C[0]), "+f"(C[1]), "+f"(C[2]), "+f"(C[3]) \
    : "r"(A[0]), "r"(A[1]), "r"(A[2]), "r"(A[3]), "r"((Bf)[0]), "r"((Bf)[1]))

#define LDSM4(R, ADDR) asm volatile( \
    "ldmatrix.sync.aligned.m8n8.x4.shared.b16 {%0,%1,%2,%3}, [%4];" \
    : "=r"((R)[0]), "=r"((R)[1]), "=r"((R)[2]), "=r"((R)[3]) : "r"(ADDR))

// ---------------- prep: weight transposes + hi/lo split + counter reset ----------------
__global__ void prep_kernel(const float* __restrict__ W5, const float* __restrict__ U5,
                            const float* __restrict__ W6, const float* __restrict__ U6) {
    int i = blockIdx.x * blockDim.x + threadIdx.x;
    if (i < 16) ((unsigned*)g_ctr2)[i] = 0u;
    const int nW5 = N3 * D1;        // 491520
    const int nU  = N3 * HQ;        // 786432
    if (i < nW5) {
        int n = i / D1, k = i % D1;
        bsplit(W5[k * N3 + n], g_W5t_hi[i], g_W5t_lo[i]);
    } else if (i < nW5 + nU) {
        int j = i - nW5; int n = j / HQ, k = j % HQ;
        bsplit(U5[k * N3 + n], g_U5t_hi[j], g_U5t_lo[j]);
    } else if (i < nW5 + 2 * nU) {
        int j = i - nW5 - nU; int n = j / HQ, k = j % HQ;
        bsplit(W6[k * N3 + n], g_W6t_hi[j], g_W6t_lo[j]);
    } else if (i < nW5 + 3 * nU) {
        int j = i - nW5 - 2 * nU; int n = j / HQ, k = j % HQ;
        bsplit(U6[k * N3 + n], g_U6t_hi[j], g_U6t_lo[j]);
    }
}

// ---------------- build X = concat(repeat(z), x2) * masks, split to bf16 hi/lo ----------------
// Vectorized: one thread handles 8 consecutive features (float4 x2 in, uint4 out).
__global__ void __launch_bounds__(256) build_x_kernel(const float* __restrict__ z,
                                                      const float* __restrict__ x2,
                                                      const float* __restrict__ masks) {
    int i = blockIdx.x * blockDim.x + threadIdx.x;      // 0 .. MROWS*40-1
    if (i >= MROWS * (D1 / 8)) return;
    int row = i / 40, cb = i - row * 40;
    int c0 = cb * 8;
    float m = masks[row];
    const float* src = (c0 < 256) ? (z + ((row >> 9) << 8) + c0)
                                  : (x2 + (size_t)row * 64 + (c0 - 256));
    float4 v0 = ((const float4*)src)[0];
    float4 v1 = ((const float4*)src)[1];
    float vv[8] = {v0.x, v0.y, v0.z, v0.w, v1.x, v1.y, v1.z, v1.w};
    __nv_bfloat16 h[8], l[8];
#pragma unroll
    for (int j = 0; j < 8; j++) bsplit(vv[j] * m, h[j], l[j]);
    size_t off = ((size_t)row * D1 + c0) / 8;
    ((uint4*)g_Xhi)[off] = *(uint4*)h;
    ((uint4*)g_Xlo)[off] = *(uint4*)l;
}

// ---------------- feedforward GEMM: g_xW = A(hi,lo) @ Wt(hi,lo)^T + bias ----------------
// Grid (24 n-tiles, 512 m-tiles) for L2 reuse of A. Block tile 128(M) x 64(N),
// BK=32, 256 threads (8 warps 4x2, warp tile 32x32). smem rows are 128B with
// 16B-chunk XOR swizzle; fragments via ldmatrix.x4 (same mapping as gru_rec).
// Register-prefetch pipeline for the next BK tile.
__global__ void __launch_bounds__(256) gemm_ff(int phase, const float* __restrict__ bias) {
    const int K = phase ? HQ : D1;
    const __nv_bfloat16* Ahi = phase ? g_g5hi : g_Xhi;
    const __nv_bfloat16* Alo = phase ? g_g5lo : g_Xlo;
    const __nv_bfloat16* Whi = phase ? g_W6t_hi : g_W5t_hi;
    const __nv_bfloat16* Wlo = phase ? g_W6t_lo : g_W5t_lo;

    __shared__ __nv_bfloat16 sAh[128 * 64], sAl[128 * 64];   // 16 KB each (128B rows)
    __shared__ __nv_bfloat16 sWh[64 * 64],  sWl[64 * 64];    // 8 KB each

    int tid = threadIdx.x;
    int row0 = blockIdx.y * 128, n0 = blockIdx.x * 64;
    int warp = tid >> 5, lane = tid & 31, g = lane >> 2, tg = lane & 3;
    int wm = warp >> 1, wn = warp & 1;
    int rm = lane & 7, jq = lane >> 3;
    int ahh = jq >> 1, bkk = jq & 1;
    int aRowL = rm + ((jq & 1) << 3);
    int bRowL = rm + ((jq >> 1) << 3);

    const unsigned bAh = (unsigned)__cvta_generic_to_shared(sAh);
    const unsigned bAl = (unsigned)__cvta_generic_to_shared(sAl);
    const unsigned bWh = (unsigned)__cvta_generic_to_shared(sWh);
    const unsigned bWl = (unsigned)__cvta_generic_to_shared(sWl);
    unsigned aOff[2], bOff[2];
#pragma unroll
    for (int mt = 0; mt < 2; mt++) aOff[mt] = (unsigned)((wm * 32 + mt * 16 + aRowL) * 128);
#pragma unroll
    for (int nh = 0; nh < 2; nh++) bOff[nh] = (unsigned)((wn * 32 + nh * 16 + bRowL) * 128);

    // staging indices: each thread stages A rows r1, r1+64 (chunk c1) and W row r1
    int r1 = tid >> 2, c1 = tid & 3;
    int swc = c1 ^ (r1 & 7);                       // (r1+64)&7 == r1&7
    unsigned stA1 = (unsigned)(r1 * 128 + swc * 16);
    unsigned stA2 = (unsigned)((r1 + 64) * 128 + swc * 16);
    unsigned stW  = stA1;

    float C[2][4][4];
#pragma unroll
    for (int a = 0; a < 2; a++)
#pragma unroll
        for (int b = 0; b < 4; b++)
#pragma unroll
            for (int c = 0; c < 4; c++) C[a][b][c] = 0.0f;

    const int nk2 = K / 32;
    uint4 ra0, ra1, rb0, rb1, rw, rv;

#define FF_LOAD(KT) do { \
        int k0 = (KT) * 32; \
        ra0 = *((const uint4*)Ahi + ((size_t)(row0 + r1) * K + k0) / 8 + c1); \
        ra1 = *((const uint4*)Ahi + ((size_t)(row0 + r1 + 64) * K + k0) / 8 + c1); \
        rb0 = *((const uint4*)Alo + ((size_t)(row0 + r1) * K + k0) / 8 + c1); \
        rb1 = *((const uint4*)Alo + ((size_t)(row0 + r1 + 64) * K + k0) / 8 + c1); \
        rw  = *((const uint4*)Whi + ((size_t)(n0 + r1) * K + k0) / 8 + c1); \
        rv  = *((const uint4*)Wlo + ((size_t)(n0 + r1) * K + k0) / 8 + c1); \
    } while (0)

    FF_LOAD(0);
    for (int kt = 0; kt < nk2; kt++) {
        *(uint4*)((char*)sAh + stA1) = ra0;
        *(uint4*)((char*)sAh + stA2) = ra1;
        *(uint4*)((char*)sAl + stA1) = rb0;
        *(uint4*)((char*)sAl + stA2) = rb1;
        *(uint4*)((char*)sWh + stW)  = rw;
        *(uint4*)((char*)sWl + stW)  = rv;
        __syncthreads();
        if (kt + 1 < nk2) FF_LOAD(kt + 1);   // overlaps MMAs below

#pragma unroll
        for (int kk = 0; kk < 2; kk++) {
            uint32_t ah4[2][4], al4[2][4], bh4[2][4], bl4[2][4];
            unsigned ac = (unsigned)(((kk * 2 + ahh) ^ rm) * 16);
            unsigned bc = (unsigned)(((kk * 2 + bkk) ^ rm) * 16);
#pragma unroll
            for (int mt = 0; mt < 2; mt++) {
                LDSM4(ah4[mt], bAh + aOff[mt] + ac);
                LDSM4(al4[mt], bAl + aOff[mt] + ac);
            }
#pragma unroll
            for (int nh = 0; nh < 2; nh++) {
                LDSM4(bh4[nh], bWh + bOff[nh] + bc);
                LDSM4(bl4[nh], bWl + bOff[nh] + bc);
            }
#pragma unroll
            for (int mt = 0; mt < 2; mt++)
#pragma unroll
                for (int nh = 0; nh < 2; nh++)
#pragma unroll
                    for (int hf = 0; hf < 2; hf++) {
                        int nt = nh * 2 + hf;
                        MMA16816(C[mt][nt], ah4[mt], bh4[nh] + 2 * hf);
                        MMA16816(C[mt][nt], ah4[mt], bl4[nh] + 2 * hf);
                        MMA16816(C[mt][nt], al4[mt], bh4[nh] + 2 * hf);
                    }
        }
        __syncthreads();
    }
    // epilogue: + bias, store fp32
#pragma unroll
    for (int mt = 0; mt < 2; mt++) {
#pragma unroll
        for (int nt = 0; nt < 4; nt++) {
            int m = row0 + wm * 32 + mt * 16 + g;
            int n = n0 + wn * 32 + nt * 8 + tg * 2;
            float b0v = bias[n], b1v = bias[n + 1];
            g_xW[(size_t)m * N3 + n]           = C[mt][nt][0] + b0v;
            g_xW[(size_t)m * N3 + n + 1]       = C[mt][nt][1] + b1v;
            g_xW[(size_t)(m + 8) * N3 + n]     = C[mt][nt][2] + b0v;
            g_xW[(size_t)(m + 8) * N3 + n + 1] = C[mt][nt][3] + b1v;
        }
    }
}

// ---------------- persistent GRU recurrence ----------------
// 128 blocks (8 batch tiles x 16 feature tiles), 384 threads (12 warps), 1 block/SM.
// Warp partition: ks (K half, 2) x gate (3) x n-half (2x16 cols).
// Step-invariant U-hi B-fragments are pinned in registers (loaded once before
// the t-loop): cuts per-warp LDSM from 64 to 48 per step.
#define SM_UHI 0
#define SM_ULO 98304
#define SM_HSH 196608
#define SM_HSL 212992
#define SM_TOTAL 229376
#define INNER_STRIDE 100
#define INNER_BYTES  6400     // 16 rows * 100 floats * 4

__global__ void __launch_bounds__(384, 1) gru_rec(int phase, const float* __restrict__ br) {
    extern __shared__ char sm[];
    const __nv_bfloat16* Uth = phase ? g_U6t_hi : g_U5t_hi;
    const __nv_bfloat16* Utl = phase ? g_U6t_lo : g_U5t_lo;
    const float* __restrict__ xW = g_xW;
    __nv_bfloat16* Ghi = phase ? g_g6hi : g_g5hi;
    __nv_bfloat16* Glo = phase ? g_g6lo : g_g5lo;

    const int tid = threadIdx.x;
    const int warp = tid >> 5, lane = tid & 31;
    const int g = lane >> 2, tg = lane & 3;
    const int bb = (int)blockIdx.x >> 4, fb = (int)blockIdx.x & 15;
    const int b0 = bb * 16, f0 = fb * 32;
    unsigned* ctr = &g_ctr2[phase][bb];

    const int ks  = warp / 6;
    const int w6  = warp % 6;
    const int gi2 = w6 >> 1;
    const int nh  = w6 & 1;
    const int rm  = lane & 7;
    const int jq  = lane >> 3;
    const int arow = rm + ((jq & 1) << 3);
    const int ahh  = jq >> 1;
    const int brow = rm + ((jq >> 1) << 3);
    const int bkk  = jq & 1;
    const int jrow0 = gi2 * 32 + nh * 16;

    const unsigned sm32 = (unsigned)__cvta_generic_to_shared(sm);
    const unsigned aBaseH = sm32 + SM_HSH + arow * 1024;
    const unsigned aBaseL = sm32 + SM_HSL + arow * 1024;
    const unsigned bBaseH = sm32 + SM_UHI + (jrow0 + brow) * 1024;
    const unsigned bBaseL = sm32 + SM_ULO + (jrow0 + brow) * 1024;

    for (int idx = tid; idx < 2 * 96 * 64; idx += 384) {
        int arr = idx >= 96 * 64;
        int e = arr ? (idx - 96 * 64) : idx;
        int j = e >> 6;
        int q = e & 63;
        int sw = q ^ (j & 7);
        int n = (j >> 5) * HQ + f0 + (j & 31);
        uint4 v = ((const uint4*)((arr ? Utl : Uth) + (size_t)n * HQ))[q];
        *(uint4*)(sm + (arr ? SM_ULO : SM_UHI) + j * 1024 + sw * 16) = v;
    }
    float bzv[2], brv[2], bhv[2];
#pragma unroll
    for (int s = 0; s < 2; s++) {
        int e = tid + s * 384;
        if (e < 512) {
            int f = f0 + (e & 31);
            bzv[s] = br[f]; brv[s] = br[512 + f]; bhv[s] = br[1024 + f];
        } else { bzv[s] = brv[s] = bhv[s] = 0.f; }
    }
    __syncthreads();

    const int ktBeg = ks * 16;

    // ---- pin step-invariant U-hi fragments in registers (16 kt x 4 regs)
    uint32_t bhp[16][4];
#pragma unroll
    for (int i = 0; i < 16; i++) {
        int kt = ktBeg + i;
        unsigned bOf = (unsigned)(((2 * kt + bkk) ^ rm) * 16);
        LDSM4(bhp[i], bBaseH + bOf);
    }

    float xzv[2], xrv[2], xhv[2], hpv[2];
#pragma unroll
    for (int s = 0; s < 2; s++) {
        int e = tid + s * 384;
        if (e < 512) {
            int r = e >> 5, c = e & 31;
            size_t row = (size_t)(b0 + r) * TQ;
            int f = f0 + c;
            xzv[s] = xW[row * N3 + f];
            xrv[s] = xW[row * N3 + 512 + f];
            xhv[s] = xW[row * N3 + 1024 + f];
        } else { xzv[s] = xrv[s] = xhv[s] = 0.f; }
    }

    for (int t = 0; t < TQ; t++) {
        if (t == 0) {
            for (int idx = tid; idx < 2048; idx += 384) {
                int arr = idx >> 10, e = idx & 1023, r = e >> 6, q = e & 63;
                int sw = q ^ (r & 7);
                *(uint4*)(sm + (arr ? SM_HSL : SM_HSH) + r * 1024 + sw * 16) =
                    make_uint4(0u, 0u, 0u, 0u);
            }
        } else {
            for (int idx = tid; idx < 2048; idx += 384) {
                int arr = idx >> 10, e = idx & 1023, r = e >> 6, q = e & 63;
                int sw = q ^ (r & 7);
                const __nv_bfloat16* src =
                    (arr ? Glo : Ghi) + ((size_t)(b0 + r) * TQ + (t - 1)) * HQ;
                uint4 v = __ldcg((const uint4*)src + q);
                *(uint4*)(sm + (arr ? SM_HSL : SM_HSH) + r * 1024 + sw * 16) = v;
            }
        }
        __syncthreads();

#pragma unroll
        for (int s = 0; s < 2; s++) {
            int e = tid + s * 384;
            hpv[s] = 0.f;
            if (e < 512) {
                int r = e >> 5, c = e & 31;
                int w = (f0 + c) >> 1;
                int sw = w ^ ((r & 7) << 2);
                uint32_t whi = *(uint32_t*)(sm + SM_HSH + r * 1024 + sw * 4);
                uint32_t wlo = *(uint32_t*)(sm + SM_HSL + r * 1024 + sw * 4);
                unsigned short sh = (c & 1) ? (unsigned short)(whi >> 16) : (unsigned short)(whi & 0xffff);
                unsigned short sl = (c & 1) ? (unsigned short)(wlo >> 16) : (unsigned short)(wlo & 0xffff);
                hpv[s] = __bfloat162float(__ushort_as_bfloat16(sh)) +
                         __bfloat162float(__ushort_as_bfloat16(sl));
            }
        }

        float C0[4] = {0.f, 0.f, 0.f, 0.f}, C1[4] = {0.f, 0.f, 0.f, 0.f};
#pragma unroll 4
        for (int i = 0; i < 16; i++) {
            int kt = ktBeg + i;
            unsigned aOf = (unsigned)(((2 * kt + ahh) ^ rm) * 16);
            unsigned bOf = (unsigned)(((2 * kt + bkk) ^ rm) * 16);
            uint32_t ah4[4], al4[4], bl4[4];
            LDSM4(ah4, aBaseH + aOf);
            LDSM4(al4, aBaseL + aOf);
            LDSM4(bl4, bBaseL + bOf);
            MMA16816(C0, ah4, bhp[i]);
            MMA16816(C0, ah4, bl4);
            MMA16816(C0, al4, bhp[i]);
            MMA16816(C1, ah4, bhp[i] + 2);
            MMA16816(C1, ah4, bl4 + 2);
            MMA16816(C1, al4, bhp[i] + 2);
        }
        __syncthreads();

        {
            float* innerK = (float*)(sm + SM_HSL + ks * INNER_BYTES);
            int colb = gi2 * 32 + nh * 16 + 2 * tg;
            innerK[g * INNER_STRIDE + colb]            = C0[0];
            innerK[g * INNER_STRIDE + colb + 1]        = C0[1];
            innerK[(g + 8) * INNER_STRIDE + colb]      = C0[2];
            innerK[(g + 8) * INNER_STRIDE + colb + 1]  = C0[3];
            innerK[g * INNER_STRIDE + colb + 8]        = C1[0];
            innerK[g * INNER_STRIDE + colb + 9]        = C1[1];
            innerK[(g + 8) * INNER_STRIDE + colb + 8]  = C1[2];
            innerK[(g + 8) * INNER_STRIDE + colb + 9]  = C1[3];
        }
        __syncthreads();

#pragma unroll
        for (int s = 0; s < 2; s++) {
            int e = tid + s * 384;
            if (e < 512) {
                int r = e >> 5, c = e & 31;
                const float* in0 = (const float*)(sm + SM_HSL);
                const float* in1 = (const float*)(sm + SM_HSL + INNER_BYTES);
                float iz = in0[r * INNER_STRIDE + c]      + in1[r * INNER_STRIDE + c];
                float ir = in0[r * INNER_STRIDE + 32 + c] + in1[r * INNER_STRIDE + 32 + c];
                float ih = in0[r * INNER_STRIDE + 64 + c] + in1[r * INNER_STRIDE + 64 + c];
                float zg = hsig(xzv[s] + iz + bzv[s]);
                float rg = hsig(xrv[s] + ir + brv[s]);
                float hh = tanhf(xhv[s] + rg * (ih + bhv[s]));
                float hn = zg * hpv[s] + (1.0f - zg) * hh;
                size_t row = (size_t)(b0 + r) * TQ + t;
                __nv_bfloat16 hi, lo; bsplit(hn, hi, lo);
                Ghi[row * HQ + f0 + c] = hi;
                Glo[row * HQ + f0 + c] = lo;
            }
        }

        if (t + 1 < TQ) {
#pragma unroll
            for (int s = 0; s < 2; s++) {
                int e = tid + s * 384;
                if (e < 512) {
                    int r = e >> 5, c = e & 31;
                    size_t row = (size_t)(b0 + r) * TQ + (t + 1);
                    int f = f0 + c;
                    xzv[s] = xW[row * N3 + f];
                    xrv[s] = xW[row * N3 + 512 + f];
                    xhv[s] = xW[row * N3 + 1024 + f];
                }
            }
        }

        __syncthreads();
        if (tid == 0) {
            asm volatile("red.release.gpu.global.add.u32 [%0], %1;" :: "l"(ctr), "r"(1u) : "memory");
            unsigned target = (unsigned)(t + 1) * 16u;
            unsigned v;
            do {
                asm volatile("ld.acquire.gpu.u32 %0, [%1];" : "=r"(v) : "l"(ctr));
                if (v >= target) break;
                __nanosleep(16);
            } while (true);
        }
        __syncthreads();
    }
}

// ---------------- final dense(1) + tanh + mask ----------------
__global__ void __launch_bounds__(256) dense_out(const float* __restrict__ Wd,
                                                 const float* __restrict__ bd,
                                                 const float* __restrict__ dmask,
                                                 float* __restrict__ out) {
    __shared__ float w[512];
    int tid = threadIdx.x;
    for (int i = tid; i < 512; i += 256) w[i] = Wd[i];
    __syncthreads();
    int warp = tid >> 5, lane = tid & 31;
    size_t row = (size_t)blockIdx.x * 8 + warp;
    const __nv_bfloat16* ph = g_g6hi + row * HQ;
    const __nv_bfloat16* pl = g_g6lo + row * HQ;
    float s = 0.f;
#pragma unroll 4
    for (int i = lane; i < 512; i += 32)
        s += (__bfloat162float(ph[i]) + __bfloat162float(pl[i])) * w[i];
#pragma unroll
    for (int o = 16; o; o >>= 1) s += __shfl_xor_sync(0xffffffffu, s, o);
    if (lane == 0) out[row] = tanhf(s + bd[0]) * dmask[row];
}

// ---------------- launch ----------------
extern "C" void kernel_launch(void* const* d_in, const int* in_sizes, int n_in,
                              void* d_out, int out_size) {
    const float* z   = (const float*)d_in[0];
    const float* x2  = (const float*)d_in[1];
    const float* msk = (const float*)d_in[2];
    const float* dmk = (const float*)d_in[3];
    const float* W5  = (const float*)d_in[4];
    const float* U5  = (const float*)d_in[5];
    const float* bi5 = (const float*)d_in[6];
    const float* br5 = (const float*)d_in[7];
    const float* W6  = (const float*)d_in[8];
    const float* U6  = (const float*)d_in[9];
    const float* bi6 = (const float*)d_in[10];
    const float* br6 = (const float*)d_in[11];
    const float* Wd  = (const float*)d_in[12];
    const float* bd  = (const float*)d_in[13];
    float* out = (float*)d_out;

    cudaFuncSetAttribute(gru_rec, cudaFuncAttributeMaxDynamicSharedMemorySize, SM_TOTAL);

    prep_kernel<<<11136, 256>>>(W5, U5, W6, U6);
    build_x_kernel<<<10240, 256>>>(z, x2, msk);
    gemm_ff<<<dim3(24, 512), 256>>>(0, bi5);
    gru_rec<<<128, 384, SM_TOTAL>>>(0, br5);
    gemm_ff<<<dim3(24, 512), 256>>>(1, bi6);
    gru_rec<<<128, 384, SM_TOTAL>>>(1, br6);
    dense_out<<<8192, 256>>>(Wd, bd, dmk, out);
}

// round 17
// speedup vs baseline: 1.5552x; 1.1071x over previous
#include <cuda_runtime.h>
#include <cuda_bf16.h>
#include <cstdint>
#include <math.h>

// Problem dims
#define BQ   128
#define TQ   512
#define HQ   512
#define N3   1536        // 3*H
#define D1   320         // LAT + F2
#define MROWS 65536      // B*T

// ---------------- scratch (__device__ globals; no runtime alloc) ----------------
__device__ __nv_bfloat16 g_Xhi[(size_t)MROWS * D1];
__device__ __nv_bfloat16 g_Xlo[(size_t)MROWS * D1];
__device__ float         g_xW [(size_t)MROWS * N3];      // reused for xW5 then xW6
__device__ __nv_bfloat16 g_g5hi[(size_t)MROWS * HQ];
__device__ __nv_bfloat16 g_g5lo[(size_t)MROWS * HQ];
__device__ __nv_bfloat16 g_g6hi[(size_t)MROWS * HQ];
__device__ __nv_bfloat16 g_g6lo[(size_t)MROWS * HQ];
__device__ __nv_bfloat16 g_W5t_hi[N3 * D1], g_W5t_lo[N3 * D1];   // [n][k]
__device__ __nv_bfloat16 g_U5t_hi[N3 * HQ], g_U5t_lo[N3 * HQ];
__device__ __nv_bfloat16 g_W6t_hi[N3 * HQ], g_W6t_lo[N3 * HQ];
__device__ __nv_bfloat16 g_U6t_hi[N3 * HQ], g_U6t_lo[N3 * HQ];
__device__ unsigned g_ctr2[2][8];      // per (phase, batch-group) barrier counters

// ---------------- helpers ----------------
__device__ __forceinline__ void bsplit(float v, __nv_bfloat16& hi, __nv_bfloat16& lo) {
    hi = __float2bfloat16_rn(v);
    lo = __float2bfloat16_rn(v - __bfloat162float(hi));
}
__device__ __forceinline__ float hsig(float x) {
    return fminf(fmaxf(0.2f * x + 0.5f, 0.0f), 1.0f);
}

#define MMA16816(C, A, Bf) asm volatile( \
    "mma.sync.aligned.m16n8k16.row.col.f32.bf16.bf16.f32 " \
    "{%0,%1,%2,%3},{%4,%5,%6,%7},{%8,%9},{%0,%1,%2,%3};\n" \
    : "+f"(C[0]), "+f"(C[1]), "+f"(C[2]), "+f"(C[3]) \
    : "r"(A[0]), "r"(A[1]), "r"(A[2]), "r"(A[3]), "r"((Bf)[0]), "r"((Bf)[1]))

#define LDSM4(R, ADDR) asm volatile( \
    "ldmatrix.sync.aligned.m8n8.x4.shared.b16 {%0,%1,%2,%3}, [%4];" \
    : "=r"((R)[0]), "=r"((R)[1]), "=r"((R)[2]), "=r"((R)[3]) : "r"(ADDR))

// ---------------- prep: weight transposes + hi/lo split + counter reset ----------------
__global__ void prep_kernel(const float* __restrict__ W5, const float* __restrict__ U5,
                            const float* __restrict__ W6, const float* __restrict__ U6) {
    int i = blockIdx.x * blockDim.x + threadIdx.x;
    if (i < 16) ((unsigned*)g_ctr2)[i] = 0u;
    const int nW5 = N3 * D1;        // 491520
    const int nU  = N3 * HQ;        // 786432
    if (i < nW5) {
        int n = i / D1, k = i % D1;
        bsplit(W5[k * N3 + n], g_W5t_hi[i], g_W5t_lo[i]);
    } else if (i < nW5 + nU) {
        int j = i - nW5; int n = j / HQ, k = j % HQ;
        bsplit(U5[k * N3 + n], g_U5t_hi[j], g_U5t_lo[j]);
    } else if (i < nW5 + 2 * nU) {
        int j = i - nW5 - nU; int n = j / HQ, k = j % HQ;
        bsplit(W6[k * N3 + n], g_W6t_hi[j], g_W6t_lo[j]);
    } else if (i < nW5 + 3 * nU) {
        int j = i - nW5 - 2 * nU; int n = j / HQ, k = j % HQ;
        bsplit(U6[k * N3 + n], g_U6t_hi[j], g_U6t_lo[j]);
    }
}

// ---------------- build X = concat(repeat(z), x2) * masks, split to bf16 hi/lo ----------------
// Vectorized: one thread handles 8 consecutive features (float4 x2 in, uint4 out).
__global__ void __launch_bounds__(256) build_x_kernel(const float* __restrict__ z,
                                                      const float* __restrict__ x2,
                                                      const float* __restrict__ masks) {
    int i = blockIdx.x * blockDim.x + threadIdx.x;      // 0 .. MROWS*40-1
    if (i >= MROWS * (D1 / 8)) return;
    int row = i / 40, cb = i - row * 40;
    int c0 = cb * 8;
    float m = masks[row];
    const float* src = (c0 < 256) ? (z + ((row >> 9) << 8) + c0)
                                  : (x2 + (size_t)row * 64 + (c0 - 256));
    float4 v0 = ((const float4*)src)[0];
    float4 v1 = ((const float4*)src)[1];
    float vv[8] = {v0.x, v0.y, v0.z, v0.w, v1.x, v1.y, v1.z, v1.w};
    __nv_bfloat16 h[8], l[8];
#pragma unroll
    for (int j = 0; j < 8; j++) bsplit(vv[j] * m, h[j], l[j]);
    size_t off = ((size_t)row * D1 + c0) / 8;
    ((uint4*)g_Xhi)[off] = *(uint4*)h;
    ((uint4*)g_Xlo)[off] = *(uint4*)l;
}

// ---------------- feedforward GEMM: g_xW = A(hi,lo) @ Wt(hi,lo)^T + bias ----------------
// Grid (24 n-tiles, 512 m-tiles) for L2 reuse of A. Block tile 128(M) x 64(N),
// BK=32, 256 threads (8 warps 4x2, warp tile 32x32). smem rows are 128B with
// 16B-chunk XOR swizzle; fragments via ldmatrix.x4 (same mapping as gru_rec).
// Register-prefetch pipeline for the next BK tile.
__global__ void __launch_bounds__(256) gemm_ff(int phase, const float* __restrict__ bias) {
    const int K = phase ? HQ : D1;
    const __nv_bfloat16* Ahi = phase ? g_g5hi : g_Xhi;
    const __nv_bfloat16* Alo = phase ? g_g5lo : g_Xlo;
    const __nv_bfloat16* Whi = phase ? g_W6t_hi : g_W5t_hi;
    const __nv_bfloat16* Wlo = phase ? g_W6t_lo : g_W5t_lo;

    __shared__ __nv_bfloat16 sAh[128 * 64], sAl[128 * 64];   // 16 KB each (128B rows)
    __shared__ __nv_bfloat16 sWh[64 * 64],  sWl[64 * 64];    // 8 KB each

    int tid = threadIdx.x;
    int row0 = blockIdx.y * 128, n0 = blockIdx.x * 64;
    int warp = tid >> 5, lane = tid & 31, g = lane >> 2, tg = lane & 3;
    int wm = warp >> 1, wn = warp & 1;
    int rm = lane & 7, jq = lane >> 3;
    int ahh = jq >> 1, bkk = jq & 1;
    int aRowL = rm + ((jq & 1) << 3);
    int bRowL = rm + ((jq >> 1) << 3);

    const unsigned bAh = (unsigned)__cvta_generic_to_shared(sAh);
    const unsigned bAl = (unsigned)__cvta_generic_to_shared(sAl);
    const unsigned bWh = (unsigned)__cvta_generic_to_shared(sWh);
    const unsigned bWl = (unsigned)__cvta_generic_to_shared(sWl);
    unsigned aOff[2], bOff[2];
#pragma unroll
    for (int mt = 0; mt < 2; mt++) aOff[mt] = (unsigned)((wm * 32 + mt * 16 + aRowL) * 128);
#pragma unroll
    for (int nh = 0; nh < 2; nh++) bOff[nh] = (unsigned)((wn * 32 + nh * 16 + bRowL) * 128);

    // staging indices: each thread stages A rows r1, r1+64 (chunk c1) and W row r1
    int r1 = tid >> 2, c1 = tid & 3;
    int swc = c1 ^ (r1 & 7);                       // (r1+64)&7 == r1&7
    unsigned stA1 = (unsigned)(r1 * 128 + swc * 16);
    unsigned stA2 = (unsigned)((r1 + 64) * 128 + swc * 16);
    unsigned stW  = stA1;

    float C[2][4][4];
#pragma unroll
    for (int a = 0; a < 2; a++)
#pragma unroll
        for (int b = 0; b < 4; b++)
#pragma unroll
            for (int c = 0; c < 4; c++) C[a][b][c] = 0.0f;

    const int nk2 = K / 32;
    uint4 ra0, ra1, rb0, rb1, rw, rv;

#define FF_LOAD(KT) do { \
        int k0 = (KT) * 32; \
        ra0 = *((const uint4*)Ahi + ((size_t)(row0 + r1) * K + k0) / 8 + c1); \
        ra1 = *((const uint4*)Ahi + ((size_t)(row0 + r1 + 64) * K + k0) / 8 + c1); \
        rb0 = *((const uint4*)Alo + ((size_t)(row0 + r1) * K + k0) / 8 + c1); \
        rb1 = *((const uint4*)Alo + ((size_t)(row0 + r1 + 64) * K + k0) / 8 + c1); \
        rw  = *((const uint4*)Whi + ((size_t)(n0 + r1) * K + k0) / 8 + c1); \
        rv  = *((const uint4*)Wlo + ((size_t)(n0 + r1) * K + k0) / 8 + c1); \
    } while (0)

    FF_LOAD(0);
    for (int kt = 0; kt < nk2; kt++) {
        *(uint4*)((char*)sAh + stA1) = ra0;
        *(uint4*)((char*)sAh + stA2) = ra1;
        *(uint4*)((char*)sAl + stA1) = rb0;
        *(uint4*)((char*)sAl + stA2) = rb1;
        *(uint4*)((char*)sWh + stW)  = rw;
        *(uint4*)((char*)sWl + stW)  = rv;
        __syncthreads();
        if (kt + 1 < nk2) FF_LOAD(kt + 1);   // overlaps MMAs below

#pragma unroll
        for (int kk = 0; kk < 2; kk++) {
            uint32_t ah4[2][4], al4[2][4], bh4[2][4], bl4[2][4];
            unsigned ac = (unsigned)(((kk * 2 + ahh) ^ rm) * 16);
            unsigned bc = (unsigned)(((kk * 2 + bkk) ^ rm) * 16);
#pragma unroll
            for (int mt = 0; mt < 2; mt++) {
                LDSM4(ah4[mt], bAh + aOff[mt] + ac);
                LDSM4(al4[mt], bAl + aOff[mt] + ac);
            }
#pragma unroll
            for (int nh = 0; nh < 2; nh++) {
                LDSM4(bh4[nh], bWh + bOff[nh] + bc);
                LDSM4(bl4[nh], bWl + bOff[nh] + bc);
            }
#pragma unroll
            for (int mt = 0; mt < 2; mt++)
#pragma unroll
                for (int nh = 0; nh < 2; nh++)
#pragma unroll
                    for (int hf = 0; hf < 2; hf++) {
                        int nt = nh * 2 + hf;
                        MMA16816(C[mt][nt], ah4[mt], bh4[nh] + 2 * hf);
                        MMA16816(C[mt][nt], ah4[mt], bl4[nh] + 2 * hf);
                        MMA16816(C[mt][nt], al4[mt], bh4[nh] + 2 * hf);
                    }
        }
        __syncthreads();
    }
    // epilogue: + bias, store fp32
#pragma unroll
    for (int mt = 0; mt < 2; mt++) {
#pragma unroll
        for (int nt = 0; nt < 4; nt++) {
            int m = row0 + wm * 32 + mt * 16 + g;
            int n = n0 + wn * 32 + nt * 8 + tg * 2;
            float b0v = bias[n], b1v = bias[n + 1];
            g_xW[(size_t)m * N3 + n]           = C[mt][nt][0] + b0v;
            g_xW[(size_t)m * N3 + n + 1]       = C[mt][nt][1] + b1v;
            g_xW[(size_t)(m + 8) * N3 + n]     = C[mt][nt][2] + b0v;
            g_xW[(size_t)(m + 8) * N3 + n + 1] = C[mt][nt][3] + b1v;
        }
    }
}

// ---------------- persistent GRU recurrence ----------------
// 128 blocks (8 batch tiles x 16 feature tiles), 384 threads (12 warps), 1 block/SM.
// Warp partition: ks (K half, 2) x gate (3) x n-half (2x16 cols).
// U-hi B-fragments pinned in registers (loaded once). Inner MMA loop is
// software-pipelined: double-buffered A/B-lo fragment sets so the LDSM for
// kt+1 issues before kt's MMAs; MMA order interleaves the two independent
// accumulator chains (C0/C1) to halve accumulate-RAW stalls.
#define SM_UHI 0
#define SM_ULO 98304
#define SM_HSH 196608
#define SM_HSL 212992
#define SM_TOTAL 229376
#define INNER_STRIDE 100
#define INNER_BYTES  6400     // 16 rows * 100 floats * 4

__global__ void __launch_bounds__(384, 1) gru_rec(int phase, const float* __restrict__ br) {
    extern __shared__ char sm[];
    const __nv_bfloat16* Uth = phase ? g_U6t_hi : g_U5t_hi;
    const __nv_bfloat16* Utl = phase ? g_U6t_lo : g_U5t_lo;
    const float* __restrict__ xW = g_xW;
    __nv_bfloat16* Ghi = phase ? g_g6hi : g_g5hi;
    __nv_bfloat16* Glo = phase ? g_g6lo : g_g5lo;

    const int tid = threadIdx.x;
    const int warp = tid >> 5, lane = tid & 31;
    const int g = lane >> 2, tg = lane & 3;
    const int bb = (int)blockIdx.x >> 4, fb = (int)blockIdx.x & 15;
    const int b0 = bb * 16, f0 = fb * 32;
    unsigned* ctr = &g_ctr2[phase][bb];

    const int ks  = warp / 6;
    const int w6  = warp % 6;
    const int gi2 = w6 >> 1;
    const int nh  = w6 & 1;
    const int rm  = lane & 7;
    const int jq  = lane >> 3;
    const int arow = rm + ((jq & 1) << 3);
    const int ahh  = jq >> 1;
    const int brow = rm + ((jq >> 1) << 3);
    const int bkk  = jq & 1;
    const int jrow0 = gi2 * 32 + nh * 16;

    const unsigned sm32 = (unsigned)__cvta_generic_to_shared(sm);
    const unsigned aBaseH = sm32 + SM_HSH + arow * 1024;
    const unsigned aBaseL = sm32 + SM_HSL + arow * 1024;
    const unsigned bBaseH = sm32 + SM_UHI + (jrow0 + brow) * 1024;
    const unsigned bBaseL = sm32 + SM_ULO + (jrow0 + brow) * 1024;

    for (int idx = tid; idx < 2 * 96 * 64; idx += 384) {
        int arr = idx >= 96 * 64;
        int e = arr ? (idx - 96 * 64) : idx;
        int j = e >> 6;
        int q = e & 63;
        int sw = q ^ (j & 7);
        int n = (j >> 5) * HQ + f0 + (j & 31);
        uint4 v = ((const uint4*)((arr ? Utl : Uth) + (size_t)n * HQ))[q];
        *(uint4*)(sm + (arr ? SM_ULO : SM_UHI) + j * 1024 + sw * 16) = v;
    }
    float bzv[2], brv[2], bhv[2];
#pragma unroll
    for (int s = 0; s < 2; s++) {
        int e = tid + s * 384;
        if (e < 512) {
            int f = f0 + (e & 31);
            bzv[s] = br[f]; brv[s] = br[512 + f]; bhv[s] = br[1024 + f];
        } else { bzv[s] = brv[s] = bhv[s] = 0.f; }
    }
    __syncthreads();

    const int ktBeg = ks * 16;

    // ---- pin step-invariant U-hi fragments in registers (16 kt x 4 regs)
    uint32_t bhp[16][4];
#pragma unroll
    for (int i = 0; i < 16; i++) {
        int kt = ktBeg + i;
        unsigned bOf = (unsigned)(((2 * kt + bkk) ^ rm) * 16);
        LDSM4(bhp[i], bBaseH + bOf);
    }

// fragment load for step-varying operands (A hi/lo from hs, B lo from U-lo)
#define GRU_LOAD(AH, AL, BL, i) do { \
        int kt_ = ktBeg + (i); \
        unsigned aOf_ = (unsigned)(((2 * kt_ + ahh) ^ rm) * 16); \
        unsigned bOf_ = (unsigned)(((2 * kt_ + bkk) ^ rm) * 16); \
        LDSM4(AH, aBaseH + aOf_); \
        LDSM4(AL, aBaseL + aOf_); \
        LDSM4(BL, bBaseL + bOf_); \
    } while (0)

// 6 MMAs for one kt, interleaving the two independent accumulator chains
#define GRU_MMA(AH, AL, BL, i) do { \
        MMA16816(C0, AH, bhp[i]);     MMA16816(C1, AH, bhp[i] + 2); \
        MMA16816(C0, AH, BL);         MMA16816(C1, AH, (BL) + 2); \
        MMA16816(C0, AL, bhp[i]);     MMA16816(C1, AL, bhp[i] + 2); \
    } while (0)

    float xzv[2], xrv[2], xhv[2], hpv[2];
#pragma unroll
    for (int s = 0; s < 2; s++) {
        int e = tid + s * 384;
        if (e < 512) {
            int r = e >> 5, c = e & 31;
            size_t row = (size_t)(b0 + r) * TQ;
            int f = f0 + c;
            xzv[s] = xW[row * N3 + f];
            xrv[s] = xW[row * N3 + 512 + f];
            xhv[s] = xW[row * N3 + 1024 + f];
        } else { xzv[s] = xrv[s] = xhv[s] = 0.f; }
    }

    for (int t = 0; t < TQ; t++) {
        if (t == 0) {
            for (int idx = tid; idx < 2048; idx += 384) {
                int arr = idx >> 10, e = idx & 1023, r = e >> 6, q = e & 63;
                int sw = q ^ (r & 7);
                *(uint4*)(sm + (arr ? SM_HSL : SM_HSH) + r * 1024 + sw * 16) =
                    make_uint4(0u, 0u, 0u, 0u);
            }
        } else {
            for (int idx = tid; idx < 2048; idx += 384) {
                int arr = idx >> 10, e = idx & 1023, r = e >> 6, q = e & 63;
                int sw = q ^ (r & 7);
                const __nv_bfloat16* src =
                    (arr ? Glo : Ghi) + ((size_t)(b0 + r) * TQ + (t - 1)) * HQ;
                uint4 v = __ldcg((const uint4*)src + q);
                *(uint4*)(sm + (arr ? SM_HSL : SM_HSH) + r * 1024 + sw * 16) = v;
            }
        }
        __syncthreads();

#pragma unroll
        for (int s = 0; s < 2; s++) {
            int e = tid + s * 384;
            hpv[s] = 0.f;
            if (e < 512) {
                int r = e >> 5, c = e & 31;
                int w = (f0 + c) >> 1;
                int sw = w ^ ((r & 7) << 2);
                uint32_t whi = *(uint32_t*)(sm + SM_HSH + r * 1024 + sw * 4);
                uint32_t wlo = *(uint32_t*)(sm + SM_HSL + r * 1024 + sw * 4);
                unsigned short sh = (c & 1) ? (unsigned short)(whi >> 16) : (unsigned short)(whi & 0xffff);
                unsigned short sl = (c & 1) ? (unsigned short)(wlo >> 16) : (unsigned short)(wlo & 0xffff);
                hpv[s] = __bfloat162float(__ushort_as_bfloat16(sh)) +
                         __bfloat162float(__ushort_as_bfloat16(sl));
            }
        }

        // ---- MMA: software-pipelined over 16 kt (double-buffered fragment sets)
        float C0[4] = {0.f, 0.f, 0.f, 0.f}, C1[4] = {0.f, 0.f, 0.f, 0.f};
        {
            uint32_t ahA[4], alA[4], blA[4], ahB[4], alB[4], blB[4];
            GRU_LOAD(ahA, alA, blA, 0);
#pragma unroll
            for (int i = 0; i < 16; i += 2) {
                GRU_LOAD(ahB, alB, blB, i + 1);
                GRU_MMA(ahA, alA, blA, i);
                if (i + 2 < 16) GRU_LOAD(ahA, alA, blA, i + 2);
                GRU_MMA(ahB, alB, blB, i + 1);
            }
        }
        __syncthreads();

        {
            float* innerK = (float*)(sm + SM_HSL + ks * INNER_BYTES);
            int colb = gi2 * 32 + nh * 16 + 2 * tg;
            innerK[g * INNER_STRIDE + colb]            = C0[0];
            innerK[g * INNER_STRIDE + colb + 1]        = C0[1];
            innerK[(g + 8) * INNER_STRIDE + colb]      = C0[2];
            innerK[(g + 8) * INNER_STRIDE + colb + 1]  = C0[3];
            innerK[g * INNER_STRIDE + colb + 8]        = C1[0];
            innerK[g * INNER_STRIDE + colb + 9]        = C1[1];
            innerK[(g + 8) * INNER_STRIDE + colb + 8]  = C1[2];
            innerK[(g + 8) * INNER_STRIDE + colb + 9]  = C1[3];
        }
        __syncthreads();

#pragma unroll
        for (int s = 0; s < 2; s++) {
            int e = tid + s * 384;
            if (e < 512) {
                int r = e >> 5, c = e & 31;
                const float* in0 = (const float*)(sm + SM_HSL);
                const float* in1 = (const float*)(sm + SM_HSL + INNER_BYTES);
                float iz = in0[r * INNER_STRIDE + c]      + in1[r * INNER_STRIDE + c];
                float ir = in0[r * INNER_STRIDE + 32 + c] + in1[r * INNER_STRIDE + 32 + c];
                float ih = in0[r * INNER_STRIDE + 64 + c] + in1[r * INNER_STRIDE + 64 + c];
                float zg = hsig(xzv[s] + iz + bzv[s]);
                float rg = hsig(xrv[s] + ir + brv[s]);
                float hh = tanhf(xhv[s] + rg * (ih + bhv[s]));
                float hn = zg * hpv[s] + (1.0f - zg) * hh;
                size_t row = (size_t)(b0 + r) * TQ + t;
                __nv_bfloat16 hi, lo; bsplit(hn, hi, lo);
                Ghi[row * HQ + f0 + c] = hi;
                Glo[row * HQ + f0 + c] = lo;
            }
        }

        if (t + 1 < TQ) {
#pragma unroll
            for (int s = 0; s < 2; s++) {
                int e = tid + s * 384;
                if (e < 512) {
                    int r = e >> 5, c = e & 31;
                    size_t row = (size_t)(b0 + r) * TQ + (t + 1);
                    int f = f0 + c;
                    xzv[s] = xW[row * N3 + f];
                    xrv[s] = xW[row * N3 + 512 + f];
                    xhv[s] = xW[row * N3 + 1024 + f];
                }
            }
        }

        __syncthreads();
        if (tid == 0) {
            asm volatile("red.release.gpu.global.add.u32 [%0], %1;" :: "l"(ctr), "r"(1u) : "memory");
            unsigned target = (unsigned)(t + 1) * 16u;
            unsigned v;
            do {
                asm volatile("ld.acquire.gpu.u32 %0, [%1];" : "=r"(v) : "l"(ctr));
                if (v >= target) break;
                __nanosleep(16);
            } while (true);
        }
        __syncthreads();
    }
}

// ---------------- final dense(1) + tanh + mask ----------------
__global__ void __launch_bounds__(256) dense_out(const float* __restrict__ Wd,
                                                 const float* __restrict__ bd,
                                                 const float* __restrict__ dmask,
                                                 float* __restrict__ out) {
    __shared__ float w[512];
    int tid = threadIdx.x;
    for (int i = tid; i < 512; i += 256) w[i] = Wd[i];
    __syncthreads();
    int warp = tid >> 5, lane = tid & 31;
    size_t row = (size_t)blockIdx.x * 8 + warp;
    const __nv_bfloat16* ph = g_g6hi + row * HQ;
    const __nv_bfloat16* pl = g_g6lo + row * HQ;
    float s = 0.f;
#pragma unroll 4
    for (int i = lane; i < 512; i += 32)
        s += (__bfloat162float(ph[i]) + __bfloat162float(pl[i])) * w[i];
#pragma unroll
    for (int o = 16; o; o >>= 1) s += __shfl_xor_sync(0xffffffffu, s, o);
    if (lane == 0) out[row] = tanhf(s + bd[0]) * dmask[row];
}

// ---------------- launch ----------------
extern "C" void kernel_launch(void* const* d_in, const int* in_sizes, int n_in,
                              void* d_out, int out_size) {
    const float* z   = (const float*)d_in[0];
    const float* x2  = (const float*)d_in[1];
    const float* msk = (const float*)d_in[2];
    const float* dmk = (const float*)d_in[3];
    const float* W5  = (const float*)d_in[4];
    const float* U5  = (const float*)d_in[5];
    const float* bi5 = (const float*)d_in[6];
    const float* br5 = (const float*)d_in[7];
    const float* W6  = (const float*)d_in[8];
    const float* U6  = (const float*)d_in[9];
    const float* bi6 = (const float*)d_in[10];
    const float* br6 = (const float*)d_in[11];
    const float* Wd  = (const float*)d_in[12];
    const float* bd  = (const float*)d_in[13];
    float* out = (float*)d_out;

    cudaFuncSetAttribute(gru_rec, cudaFuncAttributeMaxDynamicSharedMemorySize, SM_TOTAL);

    prep_kernel<<<11136, 256>>>(W5, U5, W6, U6);
    build_x_kernel<<<10240, 256>>>(z, x2, msk);
    gemm_ff<<<dim3(24, 512), 256>>>(0, bi5);
    gru_rec<<<128, 384, SM_TOTAL>>>(0, br5);
    gemm_ff<<<dim3(24, 512), 256>>>(1, bi6);
    gru_rec<<<128, 384, SM_TOTAL>>>(1, br6);
    dense_out<<<8192, 256>>>(Wd, bd, dmk, out);
}